// round 10
// baseline (speedup 1.0000x reference)
#include <cuda_runtime.h>

#define FULLMASK 0xffffffffu
#define NTAGS 32
#define BOS_IDX 30
#define EOS_IDX 31
#define L2E 1.4426950408889634f
#define LN2 0.6931471805599453f

typedef unsigned long long ull;

static __device__ __forceinline__ void ffma2(ull& d, ull a, ull b) {
    asm("fma.rn.f32x2 %0, %1, %2, %0;" : "+l"(d) : "l"(a), "l"(b));
}
static __device__ __forceinline__ ull add2(ull a, ull b) {
    ull r;
    asm("add.rn.f32x2 %0, %1, %2;" : "=l"(r) : "l"(a), "l"(b));
    return r;
}
static __device__ __forceinline__ float ex2_(float x) {
    float r; asm("ex2.approx.f32 %0, %1;" : "=f"(r) : "f"(x)); return r;
}
static __device__ __forceinline__ float lg2_(float x) {
    float r; asm("lg2.approx.f32 %0, %1;" : "=f"(r) : "f"(x)); return r;
}
static __device__ __forceinline__ float hsum2(ull a, ull b) {
    ull s = add2(a, b);
    float x, y;
    asm("mov.b64 {%0,%1}, %2;" : "=f"(x), "=f"(y) : "l"(s));
    return x + y;
}

// Half-split warp matvec (R7/R8-verified): lane l stores x_l, reads its
// 16-element half (4x LDS.128), computes half-dots for rows l and l^16,
// combines with one shfl_xor(16). No __syncwarp (convergent lanes, in-order
// per-warp LSU; verified R5/R6/R8).
static __device__ __forceinline__ float mv_half(
    unsigned stA, unsigned ldA, float x, const ull* eu, const ull* ew)
{
    asm volatile("st.shared.f32 [%0], %1;" :: "r"(stA), "f"(x) : "memory");
    ull p0, p1, p2, p3;
    asm volatile("ld.shared.v2.u64 {%0,%1}, [%2];"
                 : "=l"(p0), "=l"(p1) : "r"(ldA));
    asm volatile("ld.shared.v2.u64 {%0,%1}, [%2];"
                 : "=l"(p2), "=l"(p3) : "r"(ldA + 16));
    ull U0 = 0ull, U1 = 0ull, W0 = 0ull, W1 = 0ull;
    ffma2(U0, eu[0], p0);  ffma2(U1, eu[1], p1);
    ffma2(W0, ew[0], p0);  ffma2(W1, ew[1], p1);
    ffma2(U0, eu[2], p2);  ffma2(U1, eu[3], p3);
    ffma2(W0, ew[2], p2);  ffma2(W1, ew[3], p3);
    asm volatile("ld.shared.v2.u64 {%0,%1}, [%2];"
                 : "=l"(p0), "=l"(p1) : "r"(ldA + 32));
    asm volatile("ld.shared.v2.u64 {%0,%1}, [%2];"
                 : "=l"(p2), "=l"(p3) : "r"(ldA + 48));
    ffma2(U0, eu[4], p0);  ffma2(U1, eu[5], p1);
    ffma2(W0, ew[4], p0);  ffma2(W1, ew[5], p1);
    ffma2(U0, eu[6], p2);  ffma2(U1, eu[7], p3);
    ffma2(W0, ew[6], p2);  ffma2(W1, ew[7], p3);
    float uu = hsum2(U0, U1);
    float ww = hsum2(W0, W1);
    return uu + __shfl_xor_sync(FULLMASK, ww, 16);
}

// Forward/backward split, 128-thread CTAs so the 4 warps land on all 4 SMSPs
// (wid%4): warp = {fwd,bwd} x {seqA,seqB}. Fwd runs emissions 1..M, bwd runs
// T-1..M+1 with G^T; lag-1 log2 rescaling both sides (fwd anchored at s_EOS,
// bwd at s_0 — G's EOS column is zero). Join: Z = sum_i v_i * beta_i,
// logZ = (lg2(Z) + Cf + Cb) * ln2.
__global__ __launch_bounds__(128, 1) void crf_fb_kernel(
    const float* __restrict__ emission,   // [B, T, 32]
    const float* __restrict__ trans,      // [32, 32]
    float* __restrict__ out,              // [B]
    int B, int T)
{
    const int lane = threadIdx.x & 31;
    const int wid  = threadIdx.x >> 5;    // 0..3
    const int sq   = wid >> 1;            // 0,1: which sequence in this CTA
    const int dir  = wid & 1;             // 0 = forward, 1 = backward
    const int b    = blockIdx.x * 2 + sq;

    __shared__ __align__(16) float sx[4][2][NTAGS];   // exchange [warp][buf][tag]
    __shared__ float sfin[2][2][NTAGS];               // join vectors [seq][dir]
    __shared__ float scst[2][2];                      // join constants

    // matrix half-rows: fwd uses G rows (lane, lane^16); bwd uses G columns.
    const int h  = lane & 16;
    const int pr = lane ^ 16;
    ull eu[8], ew[8];
    #pragma unroll
    for (int q = 0; q < 8; q++) {
        float x, y, z, u;
        if (dir == 0) {
            x = expf(trans[lane * NTAGS + h + 2 * q]);
            y = expf(trans[lane * NTAGS + h + 2 * q + 1]);
            z = expf(trans[pr   * NTAGS + h + 2 * q]);
            u = expf(trans[pr   * NTAGS + h + 2 * q + 1]);
        } else {
            x = expf(trans[(h + 2 * q)     * NTAGS + lane]);
            y = expf(trans[(h + 2 * q + 1) * NTAGS + lane]);
            z = expf(trans[(h + 2 * q)     * NTAGS + pr]);
            u = expf(trans[(h + 2 * q + 1) * NTAGS + pr]);
        }
        asm("mov.b64 %0, {%1,%2};" : "=l"(eu[q]) : "f"(x), "f"(y));
        asm("mov.b64 %0, {%1,%2};" : "=l"(ew[q]) : "f"(z), "f"(u));
    }

    const float* emb = emission + (size_t)b * T * NTAGS + lane;
    const int M = (T - 1) >> 1;            // fwd: 1..M, bwd: T-1..M+1

    const unsigned sa  = (unsigned)__cvta_generic_to_shared(&sx[wid][0][0]);
    const unsigned BUF = NTAGS * 4;
    unsigned stA = sa + (unsigned)lane * 4;
    unsigned ldA = sa + (unsigned)h * 4;

    float beta, Cs, sE;
    if (dir == 0) {
        // forward init: step 0 analytic (only BOS survives), EOS-anchored
        float a2 = (emb[0] + trans[lane * NTAGS + BOS_IDX]) * L2E;
        Cs = __shfl_sync(FULLMASK, a2, EOS_IDX);
        beta = ex2_(a2 - Cs);              // 0 on dead BOS lane
        sE = 1.0f;

        float ring[4];
        #pragma unroll
        for (int i = 0; i < 4; i++) {
            int tt = (i + 1 < T) ? (i + 1) : (T - 1);
            ring[i] = emb[(size_t)tt * NTAGS];
        }

        #pragma unroll 4
        for (int it = 1; it <= M; ++it) {
            float emv = ring[0];
            ring[0] = ring[1]; ring[1] = ring[2]; ring[2] = ring[3];
            int tp = (it + 4 < T) ? (it + 4) : (T - 1);
            ring[3] = emb[(size_t)tp * NTAGS];

            float D = lg2_(sE);            // lag-1, off-chain
            Cs += D;
            float K = ex2_(fmaf(emv, L2E, -D));

            stA ^= BUF; ldA ^= BUF;
            float s = mv_half(stA, ldA, beta, eu, ew);
            sE = __shfl_sync(FULLMASK, s, EOS_IDX);
            beta = s * K;                  // post-multiply (forward)
        }
    } else {
        // backward init: v = exp(trans[EOS,:]); v_EOS = exp(-1000) = 0
        beta = expf(trans[EOS_IDX * NTAGS + lane]);
        Cs = 0.0f;
        sE = 1.0f;
        int nb = T - 1 - M;                // emissions T-1 .. M+1

        float ring[4];
        #pragma unroll
        for (int i = 0; i < 4; i++) {
            int tt = T - 1 - i; if (tt < 0) tt = 0;
            ring[i] = emb[(size_t)tt * NTAGS];
        }

        #pragma unroll 4
        for (int it = 0; it < nb; ++it) {
            float emv = ring[0];
            ring[0] = ring[1]; ring[1] = ring[2]; ring[2] = ring[3];
            int tn = T - 1 - it - 4; if (tn < 0) tn = 0;
            ring[3] = emb[(size_t)tn * NTAGS];

            float D = lg2_(sE);            // lag-1, off-chain
            Cs += D;
            float K = ex2_(fmaf(emv, L2E, -D));

            float u = beta * K;            // pre-multiply (backward)
            stA ^= BUF; ldA ^= BUF;
            float s = mv_half(stA, ldA, u, eu, ew);
            sE = __shfl_sync(FULLMASK, s, 0);   // anchor lane 0
            beta = s;
        }
    }

    // join (per sequence)
    sfin[sq][dir][lane] = beta;
    if (lane == 0) scst[sq][dir] = Cs;
    __syncthreads();

    if (dir == 0) {
        float p = sfin[sq][0][lane] * sfin[sq][1][lane];
        #pragma unroll
        for (int o = 16; o; o >>= 1)
            p += __shfl_xor_sync(FULLMASK, p, o);
        if (lane == 0)
            out[b] = (lg2_(p) + scst[sq][0] + scst[sq][1]) * LN2;
    }
}

extern "C" void kernel_launch(void* const* d_in, const int* in_sizes, int n_in,
                              void* d_out, int out_size)
{
    const float* em = (const float*)d_in[0];
    const float* tr = (const float*)d_in[1];
    long long em_elems = in_sizes[0];
    if (n_in >= 2 && in_sizes[0] == NTAGS * NTAGS && in_sizes[1] > NTAGS * NTAGS) {
        em = (const float*)d_in[1];
        tr = (const float*)d_in[0];
        em_elems = in_sizes[1];
    }

    int B = out_size;
    int T = (int)(em_elems / ((long long)B * NTAGS));

    // 128 threads = 4 warps on all 4 SMSPs: {fwd,bwd} x {2 sequences}
    int blocks = (B + 1) / 2;
    crf_fb_kernel<<<blocks, 128>>>(em, tr, (float*)d_out, B, T);
}

// round 11
// speedup vs baseline: 1.1042x; 1.1042x over previous
#include <cuda_runtime.h>

#define FULLMASK 0xffffffffu
#define NTAGS 32
#define BOS_IDX 30
#define EOS_IDX 31
#define L2E 1.4426950408889634f
#define LN2 0.6931471805599453f

typedef unsigned long long ull;

static __device__ __forceinline__ void ffma2(ull& d, ull a, ull b) {
    asm("fma.rn.f32x2 %0, %1, %2, %0;" : "+l"(d) : "l"(a), "l"(b));
}
static __device__ __forceinline__ float ex2_(float x) {
    float r; asm("ex2.approx.f32 %0, %1;" : "=f"(r) : "f"(x)); return r;
}
static __device__ __forceinline__ float lg2_(float x) {
    float r; asm("lg2.approx.f32 %0, %1;" : "=f"(r) : "f"(x)); return r;
}
static __device__ __forceinline__ float hsum2(ull a, ull b) {
    ull s;
    asm("add.rn.f32x2 %0, %1, %2;" : "=l"(s) : "l"(a), "l"(b));
    float x, y;
    asm("mov.b64 {%0,%1}, %2;" : "=f"(x), "=f"(y) : "l"(s));
    return x + y;
}

// ---------------------------------------------------------------------------
// One warp per sequence, lane = tag.  Multiplicative lag-1 recurrence in log2
// domain (R4/R8-verified numerics):
//   s_j = sum_i G[j,i]*beta_i;  beta' = s*K;  K = ex2(em*L2E - D)
//   D = lg2(s_EOS of a previous step), applied every 2nd step; Csum += D.
// Quarter-split exchange: lane l reads 8 betas (2x LDS.128, conflict-free),
// computes quarter-dots for rows {l, l^8, l^16, l^24}, combines with
// shfl_xor(8) x2 + shfl_xor(16):
//   Q0 = P0 + xor8(P1); Q1 = P2 + xor8(P3); s = Q0 + xor16(Q1).
// Emissions staged through smem: LDG.128 + STS.128 per 4 steps, LDS.32/step.
// No __syncwarp (convergent lanes, in-order per-warp LSU; R5/R6/R8-verified).
// ---------------------------------------------------------------------------

struct StepState {
    float beta, Cs, sE;
};

// one recurrence step; RESCALE decided at compile time per unrolled position
template <bool RESCALE>
static __device__ __forceinline__ void crf_step(
    StepState& st, float emt, unsigned sbw, unsigned bufoff, int lane, int c0,
    const ull* e0, const ull* e1, const ull* e2, const ull* e3)
{
    float K;
    if (RESCALE) {
        float D = lg2_(st.sE);
        st.Cs += D;
        K = ex2_(fmaf(emt, L2E, -D));
    } else {
        K = ex2_(emt * L2E);
    }

    unsigned base = sbw + bufoff;
    asm volatile("st.shared.f32 [%0], %1;"
                 :: "r"(base + (unsigned)lane * 4), "f"(st.beta) : "memory");

    unsigned bq = base + (unsigned)c0 * 4;     // this lane's 8-beta quarter
    ull p0, p1, p2, p3;
    asm volatile("ld.shared.v2.u64 {%0,%1}, [%2];"
                 : "=l"(p0), "=l"(p1) : "r"(bq));
    asm volatile("ld.shared.v2.u64 {%0,%1}, [%2];"
                 : "=l"(p2), "=l"(p3) : "r"(bq + 16));

    ull A, B;
    A = 0ull; B = 0ull;
    ffma2(A, e0[0], p0); ffma2(B, e0[1], p1);
    ffma2(A, e0[2], p2); ffma2(B, e0[3], p3);
    float P0 = hsum2(A, B);
    A = 0ull; B = 0ull;
    ffma2(A, e1[0], p0); ffma2(B, e1[1], p1);
    ffma2(A, e1[2], p2); ffma2(B, e1[3], p3);
    float P1 = hsum2(A, B);
    A = 0ull; B = 0ull;
    ffma2(A, e2[0], p0); ffma2(B, e2[1], p1);
    ffma2(A, e2[2], p2); ffma2(B, e2[3], p3);
    float P2 = hsum2(A, B);
    A = 0ull; B = 0ull;
    ffma2(A, e3[0], p0); ffma2(B, e3[1], p1);
    ffma2(A, e3[2], p2); ffma2(B, e3[3], p3);
    float P3 = hsum2(A, B);

    float Q0 = P0 + __shfl_xor_sync(FULLMASK, P1, 8);
    float Q1 = P2 + __shfl_xor_sync(FULLMASK, P3, 8);
    float s  = Q0 + __shfl_xor_sync(FULLMASK, Q1, 16);

    if (!RESCALE)  // capture anchor on non-rescale (odd) steps, lag-1
        st.sE = __shfl_sync(FULLMASK, s, EOS_IDX);
    st.beta = s * K;
}

__global__ __launch_bounds__(64, 1) void crf_forward_kernel(
    const float* __restrict__ emission,   // [B, T, 32]
    const float* __restrict__ trans,      // [32, 32]
    float* __restrict__ out,              // [B]
    int B, int T)
{
    const int lane = threadIdx.x & 31;
    const int w    = threadIdx.x >> 5;
    const int b    = blockIdx.x * 2 + w;

    __shared__ __align__(16) float sbeta[2][2][NTAGS];        // beta exchange
    __shared__ __align__(16) float sem[2][4][4 * NTAGS];      // staged emissions

    if (b >= B) return;  // warp-uniform

    // G quarter-rows for this lane: rows {l, l^8, l^16, l^24} over this lane's
    // col group c0..c0+7 (g = (l>>3)&3), packed f32x2.
    const int g  = (lane >> 3) & 3;
    const int c0 = 8 * g;
    ull e0[4], e1[4], e2[4], e3[4];
    {
        const int r0 = lane, r1 = lane ^ 8, r2 = lane ^ 16, r3 = lane ^ 24;
        #pragma unroll
        for (int p = 0; p < 4; p++) {
            float x, y;
            x = expf(trans[r0 * NTAGS + c0 + 2 * p]);
            y = expf(trans[r0 * NTAGS + c0 + 2 * p + 1]);
            asm("mov.b64 %0, {%1,%2};" : "=l"(e0[p]) : "f"(x), "f"(y));
            x = expf(trans[r1 * NTAGS + c0 + 2 * p]);
            y = expf(trans[r1 * NTAGS + c0 + 2 * p + 1]);
            asm("mov.b64 %0, {%1,%2};" : "=l"(e1[p]) : "f"(x), "f"(y));
            x = expf(trans[r2 * NTAGS + c0 + 2 * p]);
            y = expf(trans[r2 * NTAGS + c0 + 2 * p + 1]);
            asm("mov.b64 %0, {%1,%2};" : "=l"(e2[p]) : "f"(x), "f"(y));
            x = expf(trans[r3 * NTAGS + c0 + 2 * p]);
            y = expf(trans[r3 * NTAGS + c0 + 2 * p + 1]);
            asm("mov.b64 %0, {%1,%2};" : "=l"(e3[p]) : "f"(x), "f"(y));
        }
    }

    const float*  em  = emission + (size_t)b * T * NTAGS;
    const float4* em4 = (const float4*)em;     // block k = float4[k*32 + lane]

    // step 0 analytic (only BOS survives init alpha), log2 units, EOS-anchored
    StepState st;
    {
        float a2 = (em[lane] + trans[lane * NTAGS + BOS_IDX]) * L2E;
        st.Cs = __shfl_sync(FULLMASK, a2, EOS_IDX);
        st.beta = ex2_(a2 - st.Cs);          // 0 on dead BOS lane
        st.sE = 1.0f;
    }

    // emission staging: 4-slot ring of 4-timestep blocks (512B each)
    const int nblk = T >> 2;                  // T assumed multiple of 4
    const unsigned semb = (unsigned)__cvta_generic_to_shared(&sem[w][0][0]);
    const unsigned sbw  = (unsigned)__cvta_generic_to_shared(&sbeta[w][0][0]);

    #pragma unroll
    for (int k = 0; k < 3; k++) {
        float4 v = __ldg(&em4[min(k, nblk - 1) * NTAGS + lane]);
        asm volatile("st.shared.v4.f32 [%0], {%1,%2,%3,%4};"
                     :: "r"(semb + k * 512 + (unsigned)lane * 16),
                        "f"(v.x), "f"(v.y), "f"(v.z), "f"(v.w) : "memory");
    }
    float4 rv = __ldg(&em4[min(3, nblk - 1) * NTAGS + lane]);

    // steps 1..3 (block 0); parity: t odd -> no rescale, t even -> rescale
    {
        float emt;
        asm volatile("ld.shared.f32 %0, [%1];" : "=f"(emt)
                     : "r"(semb + 1 * 128 + (unsigned)lane * 4));
        crf_step<false>(st, emt, sbw, 128, lane, c0, e0, e1, e2, e3);
        if (T > 2) {
            asm volatile("ld.shared.f32 %0, [%1];" : "=f"(emt)
                         : "r"(semb + 2 * 128 + (unsigned)lane * 4));
            crf_step<true>(st, emt, sbw, 0, lane, c0, e0, e1, e2, e3);
        }
        if (T > 3) {
            asm volatile("ld.shared.f32 %0, [%1];" : "=f"(emt)
                         : "r"(semb + 3 * 128 + (unsigned)lane * 4));
            crf_step<false>(st, emt, sbw, 128, lane, c0, e0, e1, e2, e3);
        }
    }

    // blocks 1..nblk-1: stage one block per 4 steps, run 4 steps
    for (int k = 1; k < nblk; k++) {
        // store block k+2 (in rv), prefetch block k+3
        asm volatile("st.shared.v4.f32 [%0], {%1,%2,%3,%4};"
                     :: "r"(semb + (unsigned)((k + 2) & 3) * 512 +
                            (unsigned)lane * 16),
                        "f"(rv.x), "f"(rv.y), "f"(rv.z), "f"(rv.w) : "memory");
        rv = __ldg(&em4[min(k + 3, nblk - 1) * NTAGS + lane]);

        const unsigned sb = semb + (unsigned)(k & 3) * 512 + (unsigned)lane * 4;
        float emt;
        // t = 4k+0 (even: rescale), buf 0
        asm volatile("ld.shared.f32 %0, [%1];" : "=f"(emt) : "r"(sb));
        crf_step<true>(st, emt, sbw, 0, lane, c0, e0, e1, e2, e3);
        // t = 4k+1 (odd), buf 1
        asm volatile("ld.shared.f32 %0, [%1];" : "=f"(emt) : "r"(sb + 128));
        crf_step<false>(st, emt, sbw, 128, lane, c0, e0, e1, e2, e3);
        // t = 4k+2 (even: rescale), buf 0
        asm volatile("ld.shared.f32 %0, [%1];" : "=f"(emt) : "r"(sb + 256));
        crf_step<true>(st, emt, sbw, 0, lane, c0, e0, e1, e2, e3);
        // t = 4k+3 (odd), buf 1
        asm volatile("ld.shared.f32 %0, [%1];" : "=f"(emt) : "r"(sb + 384));
        crf_step<false>(st, emt, sbw, 128, lane, c0, e0, e1, e2, e3);
    }

    // materialize alpha (log2 units) and terminal lse over the warp
    float ahat = lg2_(st.beta) + st.Cs;             // -inf on BOS lane: ok
    float v = fmaf(trans[EOS_IDX * NTAGS + lane], L2E, ahat);
    float mm = v;
    #pragma unroll
    for (int o = 16; o; o >>= 1)
        mm = fmaxf(mm, __shfl_xor_sync(FULLMASK, mm, o));
    float ex = ex2_(v - mm);
    #pragma unroll
    for (int o = 16; o; o >>= 1)
        ex += __shfl_xor_sync(FULLMASK, ex, o);
    if (lane == 0)
        out[b] = (mm + lg2_(ex)) * LN2;
}

extern "C" void kernel_launch(void* const* d_in, const int* in_sizes, int n_in,
                              void* d_out, int out_size)
{
    const float* em = (const float*)d_in[0];
    const float* tr = (const float*)d_in[1];
    long long em_elems = in_sizes[0];
    if (n_in >= 2 && in_sizes[0] == NTAGS * NTAGS && in_sizes[1] > NTAGS * NTAGS) {
        em = (const float*)d_in[1];
        tr = (const float*)d_in[0];
        em_elems = in_sizes[1];
    }

    int B = out_size;
    int T = (int)(em_elems / ((long long)B * NTAGS));

    int blocks = (B + 1) / 2;  // 2 warps (2 sequences) per 64-thread CTA
    crf_forward_kernel<<<blocks, 64>>>(em, tr, (float*)d_out, B, T);
}